// round 15
// baseline (speedup 1.0000x reference)
#include <cuda_runtime.h>
#include <cuda_fp16.h>
#include <math.h>
#include <stdint.h>

// ---------------------------------------------------------------------------
// CausalTransformer: B=2, T=5120, FEAT=256, TIN=5 -> S=1024 patches
// HDIM=1024, N_HEADS=16, HEAD_DIM=64, N_LAYERS=8, FF_DIM=4096, NUM_CLASSES=100
// Round 14: revert BM=64 experiment (back to round-11 GEMM);
//           single change: flash_kernel occupancy 1 -> 2 CTAs/SM.
// ---------------------------------------------------------------------------

#define SLEN   1024
#define NB     2
#define BS     2048
#define HDIM   1024
#define INDIM  1280
#define QKVD   3072
#define FFD    4096
#define NH     16
#define HD     64
#define NC     100
#define NLAY   8
#define LREL   257

// ------------------------- scratch (device globals) ------------------------
__device__ float  g_z[(size_t)BS * HDIM];
__device__ float  g_qkv[(size_t)BS * QKVD];
__device__ float  g_ff[(size_t)BS * HDIM];
__device__ __half g_lnh[(size_t)BS * INDIM];
__device__ __half g_oh[(size_t)BS * HDIM];
__device__ __half g_ffh[(size_t)BS * FFD];
#define WOFF_PE   ((size_t)0)
#define WOFF_QKV  (WOFF_PE  + (size_t)INDIM * HDIM)
#define WOFF_OUT  (WOFF_QKV + (size_t)NLAY * QKVD * HDIM)
#define WOFF_FC1  (WOFF_OUT + (size_t)NLAY * HDIM * HDIM)
#define WOFF_FC2  (WOFF_FC1 + (size_t)NLAY * FFD * HDIM)
#define WOFF_HEAD (WOFF_FC2 + (size_t)NLAY * HDIM * FFD)
#define WTOTAL    (WOFF_HEAD + (size_t)NC * HDIM)
__device__ __half g_wh[WTOTAL];

// ---------------------------- helpers ---------------------------------------
__device__ __forceinline__ void mma_f16(float (&d)[4],
                                        const uint32_t (&a)[4],
                                        const uint32_t (&b)[2])
{
    asm volatile(
        "mma.sync.aligned.m16n8k16.row.col.f32.f16.f16.f32 "
        "{%0,%1,%2,%3}, {%4,%5,%6,%7}, {%8,%9}, {%0,%1,%2,%3};\n"
        : "+f"(d[0]), "+f"(d[1]), "+f"(d[2]), "+f"(d[3])
        : "r"(a[0]), "r"(a[1]), "r"(a[2]), "r"(a[3]),
          "r"(b[0]), "r"(b[1]));
}

__device__ __forceinline__ void ldsm_x4(uint32_t& r0, uint32_t& r1,
                                        uint32_t& r2, uint32_t& r3,
                                        uint32_t addr)
{
    asm volatile("ldmatrix.sync.aligned.m8n8.x4.shared.b16 {%0,%1,%2,%3}, [%4];"
                 : "=r"(r0), "=r"(r1), "=r"(r2), "=r"(r3) : "r"(addr));
}

__device__ __forceinline__ uint32_t smem_u32(const void* p)
{
    uint32_t a;
    asm("{ .reg .u64 t; cvta.to.shared.u64 t, %1; cvt.u32.u64 %0, t; }"
        : "=r"(a) : "l"(p));
    return a;
}

#define CP16(dst, src) \
    asm volatile("cp.async.cg.shared.global [%0], [%1], 16;" \
                 :: "r"(dst), "l"(src))

// split float into fp16 hi + fp16 lo, pack pairs into u32
__device__ __forceinline__ void hl_pack(float a, float b,
                                        uint32_t& hi, uint32_t& lo)
{
    __half ha = __float2half_rn(a), hb = __float2half_rn(b);
    __half la = __float2half_rn(a - __half2float(ha));
    __half lb = __float2half_rn(b - __half2float(hb));
    __half2 H = __halves2half2(ha, hb), L = __halves2half2(la, lb);
    hi = *(uint32_t*)&H;
    lo = *(uint32_t*)&L;
}

// --------------------------- weight fp16 conversion -------------------------
__global__ void cvt_h(const float* __restrict__ in, __half* __restrict__ out,
                      int n4)
{
    for (int i = blockIdx.x * blockDim.x + threadIdx.x; i < n4;
         i += gridDim.x * blockDim.x) {
        float4 v = ((const float4*)in)[i];
        __half2 h0 = __floats2half2_rn(v.x, v.y);
        __half2 h1 = __floats2half2_rn(v.z, v.w);
        uint2 u;
        u.x = *(uint32_t*)&h0;
        u.y = *(uint32_t*)&h1;
        ((uint2*)out)[i] = u;
    }
}

// ------------------- LayerNorm (warp/row, fully unrolled) -------------------
template<int NIT>
__global__ void ln_kernel(const float* __restrict__ in,
                          float* __restrict__ outF, __half* __restrict__ outH,
                          const float* __restrict__ g, const float* __restrict__ b,
                          float eps)
{
    const int n = NIT * 128;
    int w = threadIdx.x >> 5, lane = threadIdx.x & 31;
    int row = blockIdx.x * 8 + w;
    const float4* p4 = (const float4*)(in + (size_t)row * n);

    float4 v[NIT];
#pragma unroll
    for (int i = 0; i < NIT; i++) v[i] = p4[lane + i * 32];

    float s = 0.f, ss = 0.f;
#pragma unroll
    for (int i = 0; i < NIT; i++) {
        s  += v[i].x + v[i].y + v[i].z + v[i].w;
        ss += v[i].x * v[i].x + v[i].y * v[i].y
            + v[i].z * v[i].z + v[i].w * v[i].w;
    }
#pragma unroll
    for (int off = 16; off > 0; off >>= 1) {
        s  += __shfl_xor_sync(0xffffffffu, s, off);
        ss += __shfl_xor_sync(0xffffffffu, ss, off);
    }
    float mean = s / n;
    float var  = ss / n - mean * mean;
    float inv  = rsqrtf(var + eps);

    const float4* g4 = (const float4*)g;
    const float4* b4 = (const float4*)b;
#pragma unroll
    for (int i = 0; i < NIT; i++) {
        float4 gg = g4[lane + i * 32], bb = b4[lane + i * 32];
        float o0 = (v[i].x - mean) * inv * gg.x + bb.x;
        float o1 = (v[i].y - mean) * inv * gg.y + bb.y;
        float o2 = (v[i].z - mean) * inv * gg.z + bb.z;
        float o3 = (v[i].w - mean) * inv * gg.w + bb.w;
        if (outH) {
            __half2 h0 = __floats2half2_rn(o0, o1);
            __half2 h1 = __floats2half2_rn(o2, o3);
            uint2 u;
            u.x = *(uint32_t*)&h0;
            u.y = *(uint32_t*)&h1;
            *(uint2*)(outH + (size_t)row * n + (lane + i * 32) * 4) = u;
        } else {
            *(float4*)(outF + (size_t)row * n + (lane + i * 32) * 4) =
                make_float4(o0, o1, o2, o3);
        }
    }
}

// -------- 3-stage cp.async fp16 GEMM: C = act(A W^T + b) + res --------------
// Round-11 proven version: 128x128 tile, BK=32, 3 stages, ldmatrix fragments.
#define BKH   32
#define SH    40
#define HSTAGE ((128 + 128) * SH)
#define GH_SMEM (3 * HSTAGE * 2)

__global__ void __launch_bounds__(256, 2)
gemm_h(const __half* __restrict__ A, const __half* __restrict__ W,
       const float* __restrict__ bias, const float* __restrict__ res,
       float* __restrict__ Cf, __half* __restrict__ Ch,
       int M, int N, int K, int act)
{
    extern __shared__ __half smh[];
    int t = threadIdx.x, lane = t & 31, wid = t >> 5;
    int wm = wid & 3, wn = wid >> 2;
    int m0 = blockIdx.y * 128, n0 = blockIdx.x * 128;
    int g = lane >> 2, tt = lane & 3;
    uint32_t sbase = smem_u32(smh);

    int lr  = lane & 7, sel = lane >> 3;
    int a_r = lr + (sel & 1) * 8, a_k = (sel >> 1) * 8;
    int b_r = lr + (sel >> 1) * 8, b_k = (sel & 1) * 8;

    float acc[2][8][4];
#pragma unroll
    for (int mi = 0; mi < 2; mi++)
#pragma unroll
        for (int ni = 0; ni < 8; ni++)
#pragma unroll
            for (int c = 0; c < 4; c++) acc[mi][ni][c] = 0.f;

    int niter = K / BKH;

    auto stage = [&](int s, int k0) {
        uint32_t sb = sbase + 2 * s * HSTAGE;
#pragma unroll
        for (int u = 0; u < 4; u++) {
            int i   = t + u * 256;
            int row = (i >> 2) & 127;
            int seg = i & 3;
            int isB = i >> 9;
            uint32_t dst = sb + (uint32_t)(isB * (128 * SH * 2))
                         + (uint32_t)(row * (SH * 2) + seg * 16);
            const __half* src;
            if (isB) {
                int rw = n0 + row; if (rw >= N) rw = N - 1;
                src = W + (size_t)rw * K + k0 + seg * 8;
            } else {
                src = A + (size_t)(m0 + row) * K + k0 + seg * 8;
            }
            CP16(dst, src);
        }
        asm volatile("cp.async.commit_group;");
    };

    stage(0, 0);
    if (niter > 1) stage(1, BKH);
    int s = 0;
    for (int it = 0; it < niter; it++) {
        if (it + 1 < niter)
            asm volatile("cp.async.wait_group 1;");
        else
            asm volatile("cp.async.wait_group 0;");
        __syncthreads();

        uint32_t sA = sbase + 2 * s * HSTAGE;
        uint32_t sB = sA + 2 * 128 * SH;
#pragma unroll
        for (int ks = 0; ks < BKH; ks += 16) {
            uint32_t af[2][4], bf[8][2];
#pragma unroll
            for (int mi = 0; mi < 2; mi++) {
                int mb = wm * 32 + mi * 16;
                uint32_t addr = sA + 2 * (uint32_t)((mb + a_r) * SH + ks + a_k);
                ldsm_x4(af[mi][0], af[mi][1], af[mi][2], af[mi][3], addr);
            }
#pragma unroll
            for (int np = 0; np < 4; np++) {
                int nb = wn * 64 + np * 16;
                uint32_t addr = sB + 2 * (uint32_t)((nb + b_r) * SH + ks + b_k);
                ldsm_x4(bf[2 * np][0], bf[2 * np][1],
                        bf[2 * np + 1][0], bf[2 * np + 1][1], addr);
            }
#pragma unroll
            for (int mi = 0; mi < 2; mi++)
#pragma unroll
                for (int ni = 0; ni < 8; ni++)
                    mma_f16(acc[mi][ni], af[mi], bf[ni]);
        }

        if (it + 2 < niter) {
            int sn = s + 2; if (sn >= 3) sn -= 3;
            stage(sn, (it + 2) * BKH);
        }
        s = (s + 1 == 3) ? 0 : s + 1;
    }

    // ---------------------------- epilogue ----------------------------------
#pragma unroll
    for (int mi = 0; mi < 2; mi++) {
#pragma unroll
        for (int ni = 0; ni < 8; ni++) {
            int m = m0 + wm * 32 + mi * 16 + g;
            int n = n0 + wn * 64 + ni * 8 + tt * 2;
            if (n >= N) continue;
            float bn0 = bias[n], bn1 = bias[n + 1];
#pragma unroll
            for (int r = 0; r < 2; r++) {
                int mm = m + r * 8;
                float v0 = acc[mi][ni][r * 2 + 0] + bn0;
                float v1 = acc[mi][ni][r * 2 + 1] + bn1;
                if (act == 1) {
                    v0 = 0.5f * v0 * (1.0f + erff(v0 * 0.70710678118654752f));
                    v1 = 0.5f * v1 * (1.0f + erff(v1 * 0.70710678118654752f));
                }
                if (res) {
                    const float2 rv = *(const float2*)(res + (size_t)mm * N + n);
                    v0 += rv.x; v1 += rv.y;
                }
                if (Ch) {
                    __half2 hh = __floats2half2_rn(v0, v1);
                    *(__half2*)(Ch + (size_t)mm * N + n) = hh;
                } else {
                    *(float2*)(Cf + (size_t)mm * N + n) = make_float2(v0, v1);
                }
            }
        }
    }
}

// ---------------------- fused flash attention (fp16) ------------------------
#define KP2 72
#define PST 72
#define FA_SMEM_BYTES (260 * 4 + 3 * 32 * KP2 * 4 + 128 * PST * 2)

__global__ void __launch_bounds__(256, 2)
flash_kernel(const float* __restrict__ qkv, const float* __restrict__ rel,
             __half* __restrict__ o)
{
    extern __shared__ float sm[];
    float*    rel_s = sm;
    uint32_t* Khi = (uint32_t*)(sm + 260);
    uint32_t* Klo = Khi + 32 * KP2;
    uint32_t* Vp  = Klo + 32 * KP2;
    __half*   Ps  = (__half*)(Vp + 32 * KP2);

    int bh = blockIdx.y, b = bh >> 4, h = bh & 15;
    int qt = gridDim.x - 1 - blockIdx.x;
    int q0 = qt * 128;
    int t = threadIdx.x, lane = t & 31, w = t >> 5;
    int g = lane >> 2, tt = lane & 3;

    for (int i = t; i < LREL; i += 256) rel_s[i] = rel[h * LREL + i];

    uint32_t qh[4][4], ql[4][4];
    {
        const float* qp0 = qkv + (size_t)(b * SLEN + q0 + w * 16 + g) * QKVD + h * HD;
        const float* qp1 = qp0 + (size_t)8 * QKVD;
#pragma unroll
        for (int kc = 0; kc < 4; kc++) {
            int d0 = kc * 16 + 2 * tt;
            hl_pack(qp0[d0],     qp0[d0 + 1], qh[kc][0], ql[kc][0]);
            hl_pack(qp1[d0],     qp1[d0 + 1], qh[kc][1], ql[kc][1]);
            hl_pack(qp0[d0 + 8], qp0[d0 + 9], qh[kc][2], ql[kc][2]);
            hl_pack(qp1[d0 + 8], qp1[d0 + 9], qh[kc][3], ql[kc][3]);
        }
    }

    float oacc[8][4];
#pragma unroll
    for (int nt = 0; nt < 8; nt++)
#pragma unroll
        for (int c = 0; c < 4; c++) oacc[nt][c] = 0.f;
    float mrow0 = -1e30f, mrow1 = -1e30f;
    float lrow0 = 0.f, lrow1 = 0.f;

    int q_g0 = q0 + w * 16 + g;
    int q_g1 = q_g0 + 8;
    int qm   = w * 16 + g;

    int nkt = 2 * qt + 2;
    for (int kt = 0; kt < nkt; kt++) {
        int kk0 = kt * 64;

        {
            int kr = t >> 2;
            int dc = (t & 3) * 16;
            const float* kp = qkv + (size_t)(b * SLEN + kk0 + kr) * QKVD
                            + HDIM + h * HD + dc;
#pragma unroll
            for (int u = 0; u < 4; u++) {
                float4 k4 = *(const float4*)(kp + u * 4);
                int dp = (dc + u * 4) >> 1;
                uint32_t hi0, lo0, hi1, lo1;
                hl_pack(k4.x, k4.y, hi0, lo0);
                hl_pack(k4.z, k4.w, hi1, lo1);
                Khi[(dp    ) * KP2 + kr] = hi0;
                Klo[(dp    ) * KP2 + kr] = lo0;
                Khi[(dp + 1) * KP2 + kr] = hi1;
                Klo[(dp + 1) * KP2 + kr] = lo1;
            }
        }
        {
            int r   = t >> 3;
            int dc2 = (t & 7) * 8;
            const float* vp0 = qkv + (size_t)(b * SLEN + kk0 + 2 * r) * QKVD
                             + 2 * HDIM + h * HD + dc2;
            const float* vp1 = vp0 + QKVD;
            float4 a0 = *(const float4*)(vp0);
            float4 a1 = *(const float4*)(vp0 + 4);
            float4 b0 = *(const float4*)(vp1);
            float4 b1 = *(const float4*)(vp1 + 4);
            float va[8] = {a0.x, a0.y, a0.z, a0.w, a1.x, a1.y, a1.z, a1.w};
            float vb[8] = {b0.x, b0.y, b0.z, b0.w, b1.x, b1.y, b1.z, b1.w};
#pragma unroll
            for (int j = 0; j < 8; j++) {
                __half2 hv = __floats2half2_rn(va[j], vb[j]);
                Vp[r * KP2 + dc2 + j] = *(uint32_t*)&hv;
            }
        }
        __syncthreads();

        float sc[8][4];
#pragma unroll
        for (int nt = 0; nt < 8; nt++)
#pragma unroll
            for (int c = 0; c < 4; c++) sc[nt][c] = 0.f;

#pragma unroll
        for (int kc = 0; kc < 4; kc++) {
#pragma unroll
            for (int nt = 0; nt < 8; nt++) {
                uint32_t bh_[2], bl_[2];
                int i0 = (kc * 8 + tt) * KP2 + nt * 8 + g;
                int i1 = (kc * 8 + tt + 4) * KP2 + nt * 8 + g;
                bh_[0] = Khi[i0]; bh_[1] = Khi[i1];
                bl_[0] = Klo[i0]; bl_[1] = Klo[i1];
                mma_f16(sc[nt], qh[kc], bh_);
                mma_f16(sc[nt], qh[kc], bl_);
                mma_f16(sc[nt], ql[kc], bh_);
            }
        }

#pragma unroll
        for (int nt = 0; nt < 8; nt++) {
            int k0c = kk0 + nt * 8 + 2 * tt;
#pragma unroll
            for (int j = 0; j < 2; j++) {
                int k = k0c + j;
                int r0 = min(max(k - q_g0, -128), 128) + 128;
                int r1 = min(max(k - q_g1, -128), 128) + 128;
                float s0 = sc[nt][j]     * 0.125f + rel_s[r0];
                float s1 = sc[nt][2 + j] * 0.125f + rel_s[r1];
                sc[nt][j]     = (k > q_g0) ? -1e9f : s0;
                sc[nt][2 + j] = (k > q_g1) ? -1e9f : s1;
            }
        }

        float mx0 = -1e30f, mx1 = -1e30f;
#pragma unroll
        for (int nt = 0; nt < 8; nt++) {
            mx0 = fmaxf(mx0, fmaxf(sc[nt][0], sc[nt][1]));
            mx1 = fmaxf(mx1, fmaxf(sc[nt][2], sc[nt][3]));
        }
        mx0 = fmaxf(mx0, __shfl_xor_sync(0xffffffffu, mx0, 1));
        mx0 = fmaxf(mx0, __shfl_xor_sync(0xffffffffu, mx0, 2));
        mx1 = fmaxf(mx1, __shfl_xor_sync(0xffffffffu, mx1, 1));
        mx1 = fmaxf(mx1, __shfl_xor_sync(0xffffffffu, mx1, 2));
        float mnew0 = fmaxf(mrow0, mx0);
        float mnew1 = fmaxf(mrow1, mx1);
        float scale0 = __expf(mrow0 - mnew0);
        float scale1 = __expf(mrow1 - mnew1);

        float sum0 = 0.f, sum1 = 0.f;
#pragma unroll
        for (int nt = 0; nt < 8; nt++) {
            float p0 = __expf(sc[nt][0] - mnew0);
            float p1 = __expf(sc[nt][1] - mnew0);
            float p2 = __expf(sc[nt][2] - mnew1);
            float p3 = __expf(sc[nt][3] - mnew1);
            sum0 += p0 + p1;
            sum1 += p2 + p3;
            int kc0 = nt * 8 + 2 * tt;
            __half2 P0 = __floats2half2_rn(p0, p1);
            __half2 P1 = __floats2half2_rn(p2, p3);
            *(__half2*)&Ps[(qm    ) * PST + kc0] = P0;
            *(__half2*)&Ps[(qm + 8) * PST + kc0] = P1;
        }
        sum0 += __shfl_xor_sync(0xffffffffu, sum0, 1);
        sum0 += __shfl_xor_sync(0xffffffffu, sum0, 2);
        sum1 += __shfl_xor_sync(0xffffffffu, sum1, 1);
        sum1 += __shfl_xor_sync(0xffffffffu, sum1, 2);

        lrow0 = lrow0 * scale0 + sum0;
        lrow1 = lrow1 * scale1 + sum1;
        mrow0 = mnew0; mrow1 = mnew1;
#pragma unroll
        for (int nt = 0; nt < 8; nt++) {
            oacc[nt][0] *= scale0; oacc[nt][1] *= scale0;
            oacc[nt][2] *= scale1; oacc[nt][3] *= scale1;
        }
        __syncwarp();

#pragma unroll
        for (int kc = 0; kc < 4; kc++) {
            uint32_t af[4];
            af[0] = *(const uint32_t*)&Ps[(qm    ) * PST + kc * 16 + 2 * tt];
            af[1] = *(const uint32_t*)&Ps[(qm + 8) * PST + kc * 16 + 2 * tt];
            af[2] = *(const uint32_t*)&Ps[(qm    ) * PST + kc * 16 + 2 * tt + 8];
            af[3] = *(const uint32_t*)&Ps[(qm + 8) * PST + kc * 16 + 2 * tt + 8];
#pragma unroll
            for (int nt = 0; nt < 8; nt++) {
                uint32_t bf[2];
                bf[0] = Vp[(kc * 8 + tt)     * KP2 + nt * 8 + g];
                bf[1] = Vp[(kc * 8 + tt + 4) * KP2 + nt * 8 + g];
                mma_f16(oacc[nt], af, bf);
            }
        }
        __syncthreads();
    }

    float inv0 = 1.0f / lrow0;
    float inv1 = 1.0f / lrow1;
    __half* op = o + (size_t)(b * SLEN + q_g0) * HDIM + h * HD;
#pragma unroll
    for (int nt = 0; nt < 8; nt++) {
        int d = nt * 8 + 2 * tt;
        *(__half2*)(op + d) =
            __floats2half2_rn(oacc[nt][0] * inv0, oacc[nt][1] * inv0);
        *(__half2*)(op + (size_t)8 * HDIM + d) =
            __floats2half2_rn(oacc[nt][2] * inv1, oacc[nt][3] * inv1);
    }
}

// ------------------------------- launcher -----------------------------------
extern "C" void kernel_launch(void* const* d_in, const int* in_sizes, int n_in,
                              void* d_out, int out_size)
{
    const float* x        = (const float*)d_in[0];
    const float* pe_ln1_g = (const float*)d_in[1];
    const float* pe_ln1_b = (const float*)d_in[2];
    const float* pe_w     = (const float*)d_in[3];
    const float* pe_b     = (const float*)d_in[4];
    const float* pe_ln2_g = (const float*)d_in[5];
    const float* pe_ln2_b = (const float*)d_in[6];
    const float* lnA_g    = (const float*)d_in[7];
    const float* lnA_b    = (const float*)d_in[8];
    const float* qkv_w    = (const float*)d_in[9];
    const float* qkv_b    = (const float*)d_in[10];
    const float* out_w    = (const float*)d_in[11];
    const float* out_b    = (const float*)d_in[12];
    const float* lnF_g    = (const float*)d_in[13];
    const float* lnF_b    = (const float*)d_in[14];
    const float* fc1_w    = (const float*)d_in[15];
    const float* fc1_b    = (const float*)d_in[16];
    const float* fc2_w    = (const float*)d_in[17];
    const float* fc2_b    = (const float*)d_in[18];
    const float* relt     = (const float*)d_in[19];
    const float* final_g  = (const float*)d_in[20];
    const float* final_b  = (const float*)d_in[21];
    const float* head_w   = (const float*)d_in[22];
    const float* head_b   = (const float*)d_in[23];
    float* out = (float*)d_out;

    float *z, *qkv, *ff;
    __half *lnh, *oh, *ffh, *wh;
    cudaGetSymbolAddress((void**)&z,   g_z);
    cudaGetSymbolAddress((void**)&qkv, g_qkv);
    cudaGetSymbolAddress((void**)&ff,  g_ff);
    cudaGetSymbolAddress((void**)&lnh, g_lnh);
    cudaGetSymbolAddress((void**)&oh,  g_oh);
    cudaGetSymbolAddress((void**)&ffh, g_ffh);
    cudaGetSymbolAddress((void**)&wh,  g_wh);

    cudaFuncSetAttribute(flash_kernel,
                         cudaFuncAttributeMaxDynamicSharedMemorySize,
                         FA_SMEM_BYTES);
    cudaFuncSetAttribute(gemm_h,
                         cudaFuncAttributeMaxDynamicSharedMemorySize,
                         GH_SMEM);

    __half* wh_pe   = wh + WOFF_PE;
    __half* wh_qkv  = wh + WOFF_QKV;
    __half* wh_out  = wh + WOFF_OUT;
    __half* wh_fc1  = wh + WOFF_FC1;
    __half* wh_fc2  = wh + WOFF_FC2;
    __half* wh_head = wh + WOFF_HEAD;

    // ---- convert all weights to fp16 (rn) ----
    cvt_h<<<2048, 256>>>(pe_w,   wh_pe,   (int)((size_t)INDIM * HDIM / 4));
    cvt_h<<<2048, 256>>>(qkv_w,  wh_qkv,  (int)((size_t)NLAY * QKVD * HDIM / 4));
    cvt_h<<<2048, 256>>>(out_w,  wh_out,  (int)((size_t)NLAY * HDIM * HDIM / 4));
    cvt_h<<<2048, 256>>>(fc1_w,  wh_fc1,  (int)((size_t)NLAY * FFD * HDIM / 4));
    cvt_h<<<2048, 256>>>(fc2_w,  wh_fc2,  (int)((size_t)NLAY * HDIM * FFD / 4));
    cvt_h<<<2048, 256>>>(head_w, wh_head, (int)((size_t)NC * HDIM / 4));

    // ---- patch embed ----
    ln_kernel<10><<<BS / 8, 256>>>(x, nullptr, lnh, pe_ln1_g, pe_ln1_b, 1e-6f);
    gemm_h<<<dim3(HDIM / 128, BS / 128), 256, GH_SMEM>>>(
        lnh, wh_pe, pe_b, nullptr, ff, nullptr, BS, HDIM, INDIM, 0);
    ln_kernel<8><<<BS / 8, 256>>>(ff, z, nullptr, pe_ln2_g, pe_ln2_b, 1e-6f);

    // ---- transformer layers ----
    for (int l = 0; l < NLAY; l++) {
        ln_kernel<8><<<BS / 8, 256>>>(z, nullptr, lnh, lnA_g + (size_t)l * HDIM,
                                      lnA_b + (size_t)l * HDIM, 1e-5f);
        gemm_h<<<dim3(QKVD / 128, BS / 128), 256, GH_SMEM>>>(
            lnh, wh_qkv + (size_t)l * QKVD * HDIM, qkv_b + (size_t)l * QKVD,
            nullptr, qkv, nullptr, BS, QKVD, HDIM, 0);

        flash_kernel<<<dim3(8, NB * NH), 256, FA_SMEM_BYTES>>>(qkv, relt, oh);

        gemm_h<<<dim3(HDIM / 128, BS / 128), 256, GH_SMEM>>>(
            oh, wh_out + (size_t)l * HDIM * HDIM, out_b + (size_t)l * HDIM,
            z, z, nullptr, BS, HDIM, HDIM, 0);

        ln_kernel<8><<<BS / 8, 256>>>(z, nullptr, lnh, lnF_g + (size_t)l * HDIM,
                                      lnF_b + (size_t)l * HDIM, 1e-5f);
        gemm_h<<<dim3(FFD / 128, BS / 128), 256, GH_SMEM>>>(
            lnh, wh_fc1 + (size_t)l * FFD * HDIM, fc1_b + (size_t)l * FFD,
            nullptr, nullptr, ffh, BS, FFD, HDIM, 1);
        gemm_h<<<dim3(HDIM / 128, BS / 128), 256, GH_SMEM>>>(
            ffh, wh_fc2 + (size_t)l * HDIM * FFD, fc2_b + (size_t)l * HDIM,
            z, z, nullptr, BS, HDIM, FFD, 0);
    }

    // ---- head ----
    ln_kernel<8><<<BS / 8, 256>>>(z, nullptr, lnh, final_g, final_b, 1e-5f);
    gemm_h<<<dim3(1, BS / 128), 256, GH_SMEM>>>(
        lnh, wh_head, head_b, nullptr, out, nullptr, BS, NC, HDIM, 0);
}

// round 16
// speedup vs baseline: 1.0411x; 1.0411x over previous
#include <cuda_runtime.h>
#include <cuda_fp16.h>
#include <math.h>
#include <stdint.h>

// ---------------------------------------------------------------------------
// CausalTransformer: B=2, T=5120, FEAT=256, TIN=5 -> S=1024 patches
// HDIM=1024, N_HEADS=16, HEAD_DIM=64, N_LAYERS=8, FF_DIM=4096, NUM_CLASSES=100
// Round 16: flash back to 1 CTA/SM (round-11 proven); single fused weight
//           conversion kernel (6 launches -> 1).
// ---------------------------------------------------------------------------

#define SLEN   1024
#define NB     2
#define BS     2048
#define HDIM   1024
#define INDIM  1280
#define QKVD   3072
#define FFD    4096
#define NH     16
#define HD     64
#define NC     100
#define NLAY   8
#define LREL   257

// ------------------------- scratch (device globals) ------------------------
__device__ float  g_z[(size_t)BS * HDIM];
__device__ float  g_qkv[(size_t)BS * QKVD];
__device__ float  g_ff[(size_t)BS * HDIM];
__device__ __half g_lnh[(size_t)BS * INDIM];
__device__ __half g_oh[(size_t)BS * HDIM];
__device__ __half g_ffh[(size_t)BS * FFD];
#define WOFF_PE   ((size_t)0)
#define WOFF_QKV  (WOFF_PE  + (size_t)INDIM * HDIM)
#define WOFF_OUT  (WOFF_QKV + (size_t)NLAY * QKVD * HDIM)
#define WOFF_FC1  (WOFF_OUT + (size_t)NLAY * HDIM * HDIM)
#define WOFF_FC2  (WOFF_FC1 + (size_t)NLAY * FFD * HDIM)
#define WOFF_HEAD (WOFF_FC2 + (size_t)NLAY * HDIM * FFD)
#define WTOTAL    (WOFF_HEAD + (size_t)NC * HDIM)
__device__ __half g_wh[WTOTAL];

// ---------------------------- helpers ---------------------------------------
__device__ __forceinline__ void mma_f16(float (&d)[4],
                                        const uint32_t (&a)[4],
                                        const uint32_t (&b)[2])
{
    asm volatile(
        "mma.sync.aligned.m16n8k16.row.col.f32.f16.f16.f32 "
        "{%0,%1,%2,%3}, {%4,%5,%6,%7}, {%8,%9}, {%0,%1,%2,%3};\n"
        : "+f"(d[0]), "+f"(d[1]), "+f"(d[2]), "+f"(d[3])
        : "r"(a[0]), "r"(a[1]), "r"(a[2]), "r"(a[3]),
          "r"(b[0]), "r"(b[1]));
}

__device__ __forceinline__ void ldsm_x4(uint32_t& r0, uint32_t& r1,
                                        uint32_t& r2, uint32_t& r3,
                                        uint32_t addr)
{
    asm volatile("ldmatrix.sync.aligned.m8n8.x4.shared.b16 {%0,%1,%2,%3}, [%4];"
                 : "=r"(r0), "=r"(r1), "=r"(r2), "=r"(r3) : "r"(addr));
}

__device__ __forceinline__ uint32_t smem_u32(const void* p)
{
    uint32_t a;
    asm("{ .reg .u64 t; cvta.to.shared.u64 t, %1; cvt.u32.u64 %0, t; }"
        : "=r"(a) : "l"(p));
    return a;
}

#define CP16(dst, src) \
    asm volatile("cp.async.cg.shared.global [%0], [%1], 16;" \
                 :: "r"(dst), "l"(src))

// split float into fp16 hi + fp16 lo, pack pairs into u32
__device__ __forceinline__ void hl_pack(float a, float b,
                                        uint32_t& hi, uint32_t& lo)
{
    __half ha = __float2half_rn(a), hb = __float2half_rn(b);
    __half la = __float2half_rn(a - __half2float(ha));
    __half lb = __float2half_rn(b - __half2float(hb));
    __half2 H = __halves2half2(ha, hb), L = __halves2half2(la, lb);
    hi = *(uint32_t*)&H;
    lo = *(uint32_t*)&L;
}

// ---------------- fused weight fp16 conversion (all tensors) ----------------
// Converts 6 fp32 weight tensors into the concatenated fp16 buffer in one
// grid-stride launch. Sizes in float4 (16B) units.
__global__ void cvt_all(const float* __restrict__ s0, const float* __restrict__ s1,
                        const float* __restrict__ s2, const float* __restrict__ s3,
                        const float* __restrict__ s4, const float* __restrict__ s5,
                        __half* __restrict__ out,
                        int n0, int n1, int n2, int n3, int n4c, int n5)
{
    int c0 = n0, c1 = c0 + n1, c2 = c1 + n2, c3 = c2 + n3, c4 = c3 + n4c;
    int total = c4 + n5;
    for (int i = blockIdx.x * blockDim.x + threadIdx.x; i < total;
         i += gridDim.x * blockDim.x) {
        const float* src;
        int j;
        if      (i < c0) { src = s0; j = i; }
        else if (i < c1) { src = s1; j = i - c0; }
        else if (i < c2) { src = s2; j = i - c1; }
        else if (i < c3) { src = s3; j = i - c2; }
        else if (i < c4) { src = s4; j = i - c3; }
        else             { src = s5; j = i - c4; }
        float4 v = ((const float4*)src)[j];
        __half2 h0 = __floats2half2_rn(v.x, v.y);
        __half2 h1 = __floats2half2_rn(v.z, v.w);
        uint2 u;
        u.x = *(uint32_t*)&h0;
        u.y = *(uint32_t*)&h1;
        ((uint2*)out)[i] = u;
    }
}

// ------------------- LayerNorm (warp/row, fully unrolled) -------------------
template<int NIT>
__global__ void ln_kernel(const float* __restrict__ in,
                          float* __restrict__ outF, __half* __restrict__ outH,
                          const float* __restrict__ g, const float* __restrict__ b,
                          float eps)
{
    const int n = NIT * 128;
    int w = threadIdx.x >> 5, lane = threadIdx.x & 31;
    int row = blockIdx.x * 8 + w;
    const float4* p4 = (const float4*)(in + (size_t)row * n);

    float4 v[NIT];
#pragma unroll
    for (int i = 0; i < NIT; i++) v[i] = p4[lane + i * 32];

    float s = 0.f, ss = 0.f;
#pragma unroll
    for (int i = 0; i < NIT; i++) {
        s  += v[i].x + v[i].y + v[i].z + v[i].w;
        ss += v[i].x * v[i].x + v[i].y * v[i].y
            + v[i].z * v[i].z + v[i].w * v[i].w;
    }
#pragma unroll
    for (int off = 16; off > 0; off >>= 1) {
        s  += __shfl_xor_sync(0xffffffffu, s, off);
        ss += __shfl_xor_sync(0xffffffffu, ss, off);
    }
    float mean = s / n;
    float var  = ss / n - mean * mean;
    float inv  = rsqrtf(var + eps);

    const float4* g4 = (const float4*)g;
    const float4* b4 = (const float4*)b;
#pragma unroll
    for (int i = 0; i < NIT; i++) {
        float4 gg = g4[lane + i * 32], bb = b4[lane + i * 32];
        float o0 = (v[i].x - mean) * inv * gg.x + bb.x;
        float o1 = (v[i].y - mean) * inv * gg.y + bb.y;
        float o2 = (v[i].z - mean) * inv * gg.z + bb.z;
        float o3 = (v[i].w - mean) * inv * gg.w + bb.w;
        if (outH) {
            __half2 h0 = __floats2half2_rn(o0, o1);
            __half2 h1 = __floats2half2_rn(o2, o3);
            uint2 u;
            u.x = *(uint32_t*)&h0;
            u.y = *(uint32_t*)&h1;
            *(uint2*)(outH + (size_t)row * n + (lane + i * 32) * 4) = u;
        } else {
            *(float4*)(outF + (size_t)row * n + (lane + i * 32) * 4) =
                make_float4(o0, o1, o2, o3);
        }
    }
}

// -------- 3-stage cp.async fp16 GEMM: C = act(A W^T + b) + res --------------
// Round-11 proven version: 128x128 tile, BK=32, 3 stages, ldmatrix fragments.
#define BKH   32
#define SH    40
#define HSTAGE ((128 + 128) * SH)
#define GH_SMEM (3 * HSTAGE * 2)

__global__ void __launch_bounds__(256, 2)
gemm_h(const __half* __restrict__ A, const __half* __restrict__ W,
       const float* __restrict__ bias, const float* __restrict__ res,
       float* __restrict__ Cf, __half* __restrict__ Ch,
       int M, int N, int K, int act)
{
    extern __shared__ __half smh[];
    int t = threadIdx.x, lane = t & 31, wid = t >> 5;
    int wm = wid & 3, wn = wid >> 2;
    int m0 = blockIdx.y * 128, n0 = blockIdx.x * 128;
    int g = lane >> 2, tt = lane & 3;
    uint32_t sbase = smem_u32(smh);

    int lr  = lane & 7, sel = lane >> 3;
    int a_r = lr + (sel & 1) * 8, a_k = (sel >> 1) * 8;
    int b_r = lr + (sel >> 1) * 8, b_k = (sel & 1) * 8;

    float acc[2][8][4];
#pragma unroll
    for (int mi = 0; mi < 2; mi++)
#pragma unroll
        for (int ni = 0; ni < 8; ni++)
#pragma unroll
            for (int c = 0; c < 4; c++) acc[mi][ni][c] = 0.f;

    int niter = K / BKH;

    auto stage = [&](int s, int k0) {
        uint32_t sb = sbase + 2 * s * HSTAGE;
#pragma unroll
        for (int u = 0; u < 4; u++) {
            int i   = t + u * 256;
            int row = (i >> 2) & 127;
            int seg = i & 3;
            int isB = i >> 9;
            uint32_t dst = sb + (uint32_t)(isB * (128 * SH * 2))
                         + (uint32_t)(row * (SH * 2) + seg * 16);
            const __half* src;
            if (isB) {
                int rw = n0 + row; if (rw >= N) rw = N - 1;
                src = W + (size_t)rw * K + k0 + seg * 8;
            } else {
                src = A + (size_t)(m0 + row) * K + k0 + seg * 8;
            }
            CP16(dst, src);
        }
        asm volatile("cp.async.commit_group;");
    };

    stage(0, 0);
    if (niter > 1) stage(1, BKH);
    int s = 0;
    for (int it = 0; it < niter; it++) {
        if (it + 1 < niter)
            asm volatile("cp.async.wait_group 1;");
        else
            asm volatile("cp.async.wait_group 0;");
        __syncthreads();

        uint32_t sA = sbase + 2 * s * HSTAGE;
        uint32_t sB = sA + 2 * 128 * SH;
#pragma unroll
        for (int ks = 0; ks < BKH; ks += 16) {
            uint32_t af[2][4], bf[8][2];
#pragma unroll
            for (int mi = 0; mi < 2; mi++) {
                int mb = wm * 32 + mi * 16;
                uint32_t addr = sA + 2 * (uint32_t)((mb + a_r) * SH + ks + a_k);
                ldsm_x4(af[mi][0], af[mi][1], af[mi][2], af[mi][3], addr);
            }
#pragma unroll
            for (int np = 0; np < 4; np++) {
                int nb = wn * 64 + np * 16;
                uint32_t addr = sB + 2 * (uint32_t)((nb + b_r) * SH + ks + b_k);
                ldsm_x4(bf[2 * np][0], bf[2 * np][1],
                        bf[2 * np + 1][0], bf[2 * np + 1][1], addr);
            }
#pragma unroll
            for (int mi = 0; mi < 2; mi++)
#pragma unroll
                for (int ni = 0; ni < 8; ni++)
                    mma_f16(acc[mi][ni], af[mi], bf[ni]);
        }

        if (it + 2 < niter) {
            int sn = s + 2; if (sn >= 3) sn -= 3;
            stage(sn, (it + 2) * BKH);
        }
        s = (s + 1 == 3) ? 0 : s + 1;
    }

    // ---------------------------- epilogue ----------------------------------
#pragma unroll
    for (int mi = 0; mi < 2; mi++) {
#pragma unroll
        for (int ni = 0; ni < 8; ni++) {
            int m = m0 + wm * 32 + mi * 16 + g;
            int n = n0 + wn * 64 + ni * 8 + tt * 2;
            if (n >= N) continue;
            float bn0 = bias[n], bn1 = bias[n + 1];
#pragma unroll
            for (int r = 0; r < 2; r++) {
                int mm = m + r * 8;
                float v0 = acc[mi][ni][r * 2 + 0] + bn0;
                float v1 = acc[mi][ni][r * 2 + 1] + bn1;
                if (act == 1) {
                    v0 = 0.5f * v0 * (1.0f + erff(v0 * 0.70710678118654752f));
                    v1 = 0.5f * v1 * (1.0f + erff(v1 * 0.70710678118654752f));
                }
                if (res) {
                    const float2 rv = *(const float2*)(res + (size_t)mm * N + n);
                    v0 += rv.x; v1 += rv.y;
                }
                if (Ch) {
                    __half2 hh = __floats2half2_rn(v0, v1);
                    *(__half2*)(Ch + (size_t)mm * N + n) = hh;
                } else {
                    *(float2*)(Cf + (size_t)mm * N + n) = make_float2(v0, v1);
                }
            }
        }
    }
}

// ---------------------- fused flash attention (fp16) ------------------------
#define KP2 72
#define PST 72
#define FA_SMEM_BYTES (260 * 4 + 3 * 32 * KP2 * 4 + 128 * PST * 2)

__global__ void __launch_bounds__(256, 1)
flash_kernel(const float* __restrict__ qkv, const float* __restrict__ rel,
             __half* __restrict__ o)
{
    extern __shared__ float sm[];
    float*    rel_s = sm;
    uint32_t* Khi = (uint32_t*)(sm + 260);
    uint32_t* Klo = Khi + 32 * KP2;
    uint32_t* Vp  = Klo + 32 * KP2;
    __half*   Ps  = (__half*)(Vp + 32 * KP2);

    int bh = blockIdx.y, b = bh >> 4, h = bh & 15;
    int qt = gridDim.x - 1 - blockIdx.x;
    int q0 = qt * 128;
    int t = threadIdx.x, lane = t & 31, w = t >> 5;
    int g = lane >> 2, tt = lane & 3;

    for (int i = t; i < LREL; i += 256) rel_s[i] = rel[h * LREL + i];

    uint32_t qh[4][4], ql[4][4];
    {
        const float* qp0 = qkv + (size_t)(b * SLEN + q0 + w * 16 + g) * QKVD + h * HD;
        const float* qp1 = qp0 + (size_t)8 * QKVD;
#pragma unroll
        for (int kc = 0; kc < 4; kc++) {
            int d0 = kc * 16 + 2 * tt;
            hl_pack(qp0[d0],     qp0[d0 + 1], qh[kc][0], ql[kc][0]);
            hl_pack(qp1[d0],     qp1[d0 + 1], qh[kc][1], ql[kc][1]);
            hl_pack(qp0[d0 + 8], qp0[d0 + 9], qh[kc][2], ql[kc][2]);
            hl_pack(qp1[d0 + 8], qp1[d0 + 9], qh[kc][3], ql[kc][3]);
        }
    }

    float oacc[8][4];
#pragma unroll
    for (int nt = 0; nt < 8; nt++)
#pragma unroll
        for (int c = 0; c < 4; c++) oacc[nt][c] = 0.f;
    float mrow0 = -1e30f, mrow1 = -1e30f;
    float lrow0 = 0.f, lrow1 = 0.f;

    int q_g0 = q0 + w * 16 + g;
    int q_g1 = q_g0 + 8;
    int qm   = w * 16 + g;

    int nkt = 2 * qt + 2;
    for (int kt = 0; kt < nkt; kt++) {
        int kk0 = kt * 64;

        {
            int kr = t >> 2;
            int dc = (t & 3) * 16;
            const float* kp = qkv + (size_t)(b * SLEN + kk0 + kr) * QKVD
                            + HDIM + h * HD + dc;
#pragma unroll
            for (int u = 0; u < 4; u++) {
                float4 k4 = *(const float4*)(kp + u * 4);
                int dp = (dc + u * 4) >> 1;
                uint32_t hi0, lo0, hi1, lo1;
                hl_pack(k4.x, k4.y, hi0, lo0);
                hl_pack(k4.z, k4.w, hi1, lo1);
                Khi[(dp    ) * KP2 + kr] = hi0;
                Klo[(dp    ) * KP2 + kr] = lo0;
                Khi[(dp + 1) * KP2 + kr] = hi1;
                Klo[(dp + 1) * KP2 + kr] = lo1;
            }
        }
        {
            int r   = t >> 3;
            int dc2 = (t & 7) * 8;
            const float* vp0 = qkv + (size_t)(b * SLEN + kk0 + 2 * r) * QKVD
                             + 2 * HDIM + h * HD + dc2;
            const float* vp1 = vp0 + QKVD;
            float4 a0 = *(const float4*)(vp0);
            float4 a1 = *(const float4*)(vp0 + 4);
            float4 b0 = *(const float4*)(vp1);
            float4 b1 = *(const float4*)(vp1 + 4);
            float va[8] = {a0.x, a0.y, a0.z, a0.w, a1.x, a1.y, a1.z, a1.w};
            float vb[8] = {b0.x, b0.y, b0.z, b0.w, b1.x, b1.y, b1.z, b1.w};
#pragma unroll
            for (int j = 0; j < 8; j++) {
                __half2 hv = __floats2half2_rn(va[j], vb[j]);
                Vp[r * KP2 + dc2 + j] = *(uint32_t*)&hv;
            }
        }
        __syncthreads();

        float sc[8][4];
#pragma unroll
        for (int nt = 0; nt < 8; nt++)
#pragma unroll
            for (int c = 0; c < 4; c++) sc[nt][c] = 0.f;

#pragma unroll
        for (int kc = 0; kc < 4; kc++) {
#pragma unroll
            for (int nt = 0; nt < 8; nt++) {
                uint32_t bh_[2], bl_[2];
                int i0 = (kc * 8 + tt) * KP2 + nt * 8 + g;
                int i1 = (kc * 8 + tt + 4) * KP2 + nt * 8 + g;
                bh_[0] = Khi[i0]; bh_[1] = Khi[i1];
                bl_[0] = Klo[i0]; bl_[1] = Klo[i1];
                mma_f16(sc[nt], qh[kc], bh_);
                mma_f16(sc[nt], qh[kc], bl_);
                mma_f16(sc[nt], ql[kc], bh_);
            }
        }

#pragma unroll
        for (int nt = 0; nt < 8; nt++) {
            int k0c = kk0 + nt * 8 + 2 * tt;
#pragma unroll
            for (int j = 0; j < 2; j++) {
                int k = k0c + j;
                int r0 = min(max(k - q_g0, -128), 128) + 128;
                int r1 = min(max(k - q_g1, -128), 128) + 128;
                float s0 = sc[nt][j]     * 0.125f + rel_s[r0];
                float s1 = sc[nt][2 + j] * 0.125f + rel_s[r1];
                sc[nt][j]     = (k > q_g0) ? -1e9f : s0;
                sc[nt][2 + j] = (k > q_g1) ? -1e9f : s1;
            }
        }

        float mx0 = -1e30f, mx1 = -1e30f;
#pragma unroll
        for (int nt = 0; nt < 8; nt++) {
            mx0 = fmaxf(mx0, fmaxf(sc[nt][0], sc[nt][1]));
            mx1 = fmaxf(mx1, fmaxf(sc[nt][2], sc[nt][3]));
        }
        mx0 = fmaxf(mx0, __shfl_xor_sync(0xffffffffu, mx0, 1));
        mx0 = fmaxf(mx0, __shfl_xor_sync(0xffffffffu, mx0, 2));
        mx1 = fmaxf(mx1, __shfl_xor_sync(0xffffffffu, mx1, 1));
        mx1 = fmaxf(mx1, __shfl_xor_sync(0xffffffffu, mx1, 2));
        float mnew0 = fmaxf(mrow0, mx0);
        float mnew1 = fmaxf(mrow1, mx1);
        float scale0 = __expf(mrow0 - mnew0);
        float scale1 = __expf(mrow1 - mnew1);

        float sum0 = 0.f, sum1 = 0.f;
#pragma unroll
        for (int nt = 0; nt < 8; nt++) {
            float p0 = __expf(sc[nt][0] - mnew0);
            float p1 = __expf(sc[nt][1] - mnew0);
            float p2 = __expf(sc[nt][2] - mnew1);
            float p3 = __expf(sc[nt][3] - mnew1);
            sum0 += p0 + p1;
            sum1 += p2 + p3;
            int kc0 = nt * 8 + 2 * tt;
            __half2 P0 = __floats2half2_rn(p0, p1);
            __half2 P1 = __floats2half2_rn(p2, p3);
            *(__half2*)&Ps[(qm    ) * PST + kc0] = P0;
            *(__half2*)&Ps[(qm + 8) * PST + kc0] = P1;
        }
        sum0 += __shfl_xor_sync(0xffffffffu, sum0, 1);
        sum0 += __shfl_xor_sync(0xffffffffu, sum0, 2);
        sum1 += __shfl_xor_sync(0xffffffffu, sum1, 1);
        sum1 += __shfl_xor_sync(0xffffffffu, sum1, 2);

        lrow0 = lrow0 * scale0 + sum0;
        lrow1 = lrow1 * scale1 + sum1;
        mrow0 = mnew0; mrow1 = mnew1;
#pragma unroll
        for (int nt = 0; nt < 8; nt++) {
            oacc[nt][0] *= scale0; oacc[nt][1] *= scale0;
            oacc[nt][2] *= scale1; oacc[nt][3] *= scale1;
        }
        __syncwarp();

#pragma unroll
        for (int kc = 0; kc < 4; kc++) {
            uint32_t af[4];
            af[0] = *(const uint32_t*)&Ps[(qm    ) * PST + kc * 16 + 2 * tt];
            af[1] = *(const uint32_t*)&Ps[(qm + 8) * PST + kc * 16 + 2 * tt];
            af[2] = *(const uint32_t*)&Ps[(qm    ) * PST + kc * 16 + 2 * tt + 8];
            af[3] = *(const uint32_t*)&Ps[(qm + 8) * PST + kc * 16 + 2 * tt + 8];
#pragma unroll
            for (int nt = 0; nt < 8; nt++) {
                uint32_t bf[2];
                bf[0] = Vp[(kc * 8 + tt)     * KP2 + nt * 8 + g];
                bf[1] = Vp[(kc * 8 + tt + 4) * KP2 + nt * 8 + g];
                mma_f16(oacc[nt], af, bf);
            }
        }
        __syncthreads();
    }

    float inv0 = 1.0f / lrow0;
    float inv1 = 1.0f / lrow1;
    __half* op = o + (size_t)(b * SLEN + q_g0) * HDIM + h * HD;
#pragma unroll
    for (int nt = 0; nt < 8; nt++) {
        int d = nt * 8 + 2 * tt;
        *(__half2*)(op + d) =
            __floats2half2_rn(oacc[nt][0] * inv0, oacc[nt][1] * inv0);
        *(__half2*)(op + (size_t)8 * HDIM + d) =
            __floats2half2_rn(oacc[nt][2] * inv1, oacc[nt][3] * inv1);
    }
}

// ------------------------------- launcher -----------------------------------
extern "C" void kernel_launch(void* const* d_in, const int* in_sizes, int n_in,
                              void* d_out, int out_size)
{
    const float* x        = (const float*)d_in[0];
    const float* pe_ln1_g = (const float*)d_in[1];
    const float* pe_ln1_b = (const float*)d_in[2];
    const float* pe_w     = (const float*)d_in[3];
    const float* pe_b     = (const float*)d_in[4];
    const float* pe_ln2_g = (const float*)d_in[5];
    const float* pe_ln2_b = (const float*)d_in[6];
    const float* lnA_g    = (const float*)d_in[7];
    const float* lnA_b    = (const float*)d_in[8];
    const float* qkv_w    = (const float*)d_in[9];
    const float* qkv_b    = (const float*)d_in[10];
    const float* out_w    = (const float*)d_in[11];
    const float* out_b    = (const float*)d_in[12];
    const float* lnF_g    = (const float*)d_in[13];
    const float* lnF_b    = (const float*)d_in[14];
    const float* fc1_w    = (const float*)d_in[15];
    const float* fc1_b    = (const float*)d_in[16];
    const float* fc2_w    = (const float*)d_in[17];
    const float* fc2_b    = (const float*)d_in[18];
    const float* relt     = (const float*)d_in[19];
    const float* final_g  = (const float*)d_in[20];
    const float* final_b  = (const float*)d_in[21];
    const float* head_w   = (const float*)d_in[22];
    const float* head_b   = (const float*)d_in[23];
    float* out = (float*)d_out;

    float *z, *qkv, *ff;
    __half *lnh, *oh, *ffh, *wh;
    cudaGetSymbolAddress((void**)&z,   g_z);
    cudaGetSymbolAddress((void**)&qkv, g_qkv);
    cudaGetSymbolAddress((void**)&ff,  g_ff);
    cudaGetSymbolAddress((void**)&lnh, g_lnh);
    cudaGetSymbolAddress((void**)&oh,  g_oh);
    cudaGetSymbolAddress((void**)&ffh, g_ffh);
    cudaGetSymbolAddress((void**)&wh,  g_wh);

    cudaFuncSetAttribute(flash_kernel,
                         cudaFuncAttributeMaxDynamicSharedMemorySize,
                         FA_SMEM_BYTES);
    cudaFuncSetAttribute(gemm_h,
                         cudaFuncAttributeMaxDynamicSharedMemorySize,
                         GH_SMEM);

    __half* wh_pe   = wh + WOFF_PE;
    __half* wh_qkv  = wh + WOFF_QKV;
    __half* wh_out  = wh + WOFF_OUT;
    __half* wh_fc1  = wh + WOFF_FC1;
    __half* wh_fc2  = wh + WOFF_FC2;
    __half* wh_head = wh + WOFF_HEAD;

    // ---- fused weight fp16 conversion (order matches g_wh layout) ----
    cvt_all<<<2048, 256>>>(pe_w, qkv_w, out_w, fc1_w, fc2_w, head_w, wh,
                           (int)((size_t)INDIM * HDIM / 4),
                           (int)((size_t)NLAY * QKVD * HDIM / 4),
                           (int)((size_t)NLAY * HDIM * HDIM / 4),
                           (int)((size_t)NLAY * FFD * HDIM / 4),
                           (int)((size_t)NLAY * HDIM * FFD / 4),
                           (int)((size_t)NC * HDIM / 4));

    // ---- patch embed ----
    ln_kernel<10><<<BS / 8, 256>>>(x, nullptr, lnh, pe_ln1_g, pe_ln1_b, 1e-6f);
    gemm_h<<<dim3(HDIM / 128, BS / 128), 256, GH_SMEM>>>(
        lnh, wh_pe, pe_b, nullptr, ff, nullptr, BS, HDIM, INDIM, 0);
    ln_kernel<8><<<BS / 8, 256>>>(ff, z, nullptr, pe_ln2_g, pe_ln2_b, 1e-6f);

    // ---- transformer layers ----
    for (int l = 0; l < NLAY; l++) {
        ln_kernel<8><<<BS / 8, 256>>>(z, nullptr, lnh, lnA_g + (size_t)l * HDIM,
                                      lnA_b + (size_t)l * HDIM, 1e-5f);
        gemm_h<<<dim3(QKVD / 128, BS / 128), 256, GH_SMEM>>>(
            lnh, wh_qkv + (size_t)l * QKVD * HDIM, qkv_b + (size_t)l * QKVD,
            nullptr, qkv, nullptr, BS, QKVD, HDIM, 0);

        flash_kernel<<<dim3(8, NB * NH), 256, FA_SMEM_BYTES>>>(qkv, relt, oh);

        gemm_h<<<dim3(HDIM / 128, BS / 128), 256, GH_SMEM>>>(
            oh, wh_out + (size_t)l * HDIM * HDIM, out_b + (size_t)l * HDIM,
            z, z, nullptr, BS, HDIM, HDIM, 0);

        ln_kernel<8><<<BS / 8, 256>>>(z, nullptr, lnh, lnF_g + (size_t)l * HDIM,
                                      lnF_b + (size_t)l * HDIM, 1e-5f);
        gemm_h<<<dim3(FFD / 128, BS / 128), 256, GH_SMEM>>>(
            lnh, wh_fc1 + (size_t)l * FFD * HDIM, fc1_b + (size_t)l * FFD,
            nullptr, nullptr, ffh, BS, FFD, HDIM, 1);
        gemm_h<<<dim3(HDIM / 128, BS / 128), 256, GH_SMEM>>>(
            ffh, wh_fc2 + (size_t)l * HDIM * FFD, fc2_b + (size_t)l * HDIM,
            z, z, nullptr, BS, HDIM, FFD, 0);
    }

    // ---- head ----
    ln_kernel<8><<<BS / 8, 256>>>(z, nullptr, lnh, final_g, final_b, 1e-5f);
    gemm_h<<<dim3(1, BS / 128), 256, GH_SMEM>>>(
        lnh, wh_head, head_b, nullptr, out, nullptr, BS, NC, HDIM, 0);
}